// round 16
// baseline (speedup 1.0000x reference)
#include <cuda_runtime.h>
#include <math.h>

#define B 16
#define I_IN 256
#define H 512
#define O_OUT 256
#define A 1024
#define M 64
#define R 4
#define IFW 471
#define N4H 2048
#define NCOLS3 (IFW + O_OUT)   // 727

// interface offsets
#define OFF_KR     0
#define OFF_BETAR  256
#define OFF_KW     260
#define OFF_BETAW  324
#define OFF_ERASE  325
#define OFF_WRITEV 389
#define OFF_FREE   453
#define OFF_GA     457
#define OFF_GW     458
#define OFF_PI     459

// skewed pack index: groups of 16 doubles padded to 18 (conflict-free for
// lane-stride-144B patterns)
#define PACKN (18 * 256)
__device__ __forceinline__ int packIdx(int a) { return 18 * (a >> 2) + 4 * (a & 3); }

// ----------------- device scratch -----------------
__device__ float  g_zpart[32][B][N4H];
__device__ float  g_iface[B][IFW];
__device__ float  g_outhid[B][O_OUT];
__device__ float  g_alloc[B][A];
__device__ float  g_cwexp[B][A];
__device__ float  g_cwpart[B][8];
__device__ float  g_ww[B][A];
__device__ float  g_S[B][R];
__device__ float  g_T[B][R];
__device__ float  g_mem[B][A][M];
__device__ float  g_cr[B][R][A];
__device__ double g_PQ[B][R][A];        // packed (p,q)
__device__ double g_UVp[16][B][R][A];   // packed (u,v) partials per stripe

__device__ __forceinline__ float sigf(float x) { return 1.f / (1.f + __expf(-x)); }
__device__ __forceinline__ float oneplusf(float x) {
    return 1.f + (x > 20.f ? x : log1pf(__expf(x)));
}

// packed f32x2 helpers (double as bit-carrier)
__device__ __forceinline__ double pack2(float lo, float hi) {
    double d; asm("mov.b64 %0, {%1,%2};" : "=d"(d) : "f"(lo), "f"(hi)); return d;
}
__device__ __forceinline__ double splat2(float v) {
    double d; asm("mov.b64 %0, {%1,%1};" : "=d"(d) : "f"(v)); return d;
}
__device__ __forceinline__ void fma2(double& acc, double a, double b) {
    asm("fma.rn.f32x2 %0, %1, %2, %3;" : "=d"(acc) : "d"(a), "d"(b), "d"(acc));
}
__device__ __forceinline__ double add2(double a, double b) {
    double d; asm("add.rn.f32x2 %0, %1, %2;" : "=d"(d) : "d"(a), "d"(b)); return d;
}
__device__ __forceinline__ float2 unpack2(double d) {
    float2 f;
    asm("mov.b64 {%0,%1}, %2;" : "=f"(f.x), "=f"(f.y) : "l"(__double_as_longlong(d)));
    return f;
}

template <int NT>
__device__ __forceinline__ float blockSum(float v, float* s_red) {
    int lane = threadIdx.x & 31, w = threadIdx.x >> 5;
#pragma unroll
    for (int o = 16; o; o >>= 1) v += __shfl_down_sync(0xffffffffu, v, o);
    if (lane == 0) s_red[w] = v;
    __syncthreads();
    if (w == 0) {
        float x = (lane < NT / 32) ? s_red[lane] : 0.f;
#pragma unroll
        for (int o = 16; o; o >>= 1) x += __shfl_down_sync(0xffffffffu, x, o);
        if (lane == 0) s_red[0] = x;
    }
    __syncthreads();
    float res = s_red[0];
    __syncthreads();
    return res;
}
template <int NT>
__device__ __forceinline__ float blockMax(float v, float* s_red) {
    int lane = threadIdx.x & 31, w = threadIdx.x >> 5;
#pragma unroll
    for (int o = 16; o; o >>= 1) v = fmaxf(v, __shfl_down_sync(0xffffffffu, v, o));
    if (lane == 0) s_red[w] = v;
    __syncthreads();
    if (w == 0) {
        float x = (lane < NT / 32) ? s_red[lane] : -1e30f;
#pragma unroll
        for (int o = 16; o; o >>= 1) x = fmaxf(x, __shfl_down_sync(0xffffffffu, x, o));
        if (lane == 0) s_red[0] = x;
    }
    __syncthreads();
    float res = s_red[0];
    __syncthreads();
    return res;
}

// ============ K1: z GEMM, k-split 32 chunks of 32, packed f32x2 (128 blocks) ============
__global__ void __launch_bounds__(256, 1)
k1_zpart(const float* __restrict__ x, const float* __restrict__ h_prev,
         const float* __restrict__ rv_prev, const float* __restrict__ Wx,
         const float* __restrict__ Wh) {
    __shared__ double s_in2[B][32];
    int tid = threadIdx.x;
    int ntile = blockIdx.x;
    int kc = blockIdx.y;
    int kbase = kc * 32;
    for (int idx = tid; idx < B * 32; idx += 256) {
        int b = idx >> 5, kl = idx & 31;
        int kk = kbase + kl;
        float v;
        if (kk < 256) v = x[b * I_IN + kk];
        else if (kk < 512) v = rv_prev[b * 256 + (kk - 256)];
        else v = h_prev[b * H + (kk - 512)];
        s_in2[b][kl] = splat2(v);
    }
    __syncthreads();
    int n0 = ntile * 512 + tid * 2;
    const float* Wbase = (kbase < 512) ? (Wx + (size_t)kbase * N4H)
                                       : (Wh + (size_t)(kbase - 512) * N4H);
    const char* Wp = (const char*)(Wbase + n0);
    double acc2[B];
#pragma unroll
    for (int b = 0; b < B; b++) acc2[b] = 0.0;
#pragma unroll 4
    for (int kl = 0; kl < 32; kl++) {
        double w2 = *(const double*)(Wp + (size_t)kl * (N4H * 4));
#pragma unroll
        for (int b = 0; b < B; b++) fma2(acc2[b], s_in2[b][kl], w2);
    }
#pragma unroll
    for (int b = 0; b < B; b++)
        *(double*)&g_zpart[kc][b][n0] = acc2[b];
}

// ============ K23: LSTM (z reduce) + iface/out_hidden GEMM, grid (2, B) ============
__global__ void __launch_bounds__(736, 1)
k23_lstm_iface(const float* __restrict__ c_prev, const float* __restrict__ b_lstm,
               const float* __restrict__ W_if, const float* __restrict__ W_hid,
               const float* __restrict__ b_if, const float* __restrict__ b_hid) {
    __shared__ float s_h[H];
    int tid = threadIdx.x;
    int half = blockIdx.x;
    int b = blockIdx.y;

    if (tid < H) {
        float zv[4];
#pragma unroll
        for (int g = 0; g < 4; g++) {
            int n = g * H + tid;
            float s = b_lstm[n];
#pragma unroll
            for (int kc = 0; kc < 32; kc++) s += g_zpart[kc][b][n];
            zv[g] = s;
        }
        float c = sigf(zv[1]) * c_prev[b * H + tid] + sigf(zv[0]) * tanhf(zv[2]);
        s_h[tid] = sigf(zv[3]) * tanhf(c);
    }
    __syncthreads();

    int col = half * 368 + tid;
    if (tid < 368 && col < NCOLS3) {
        float a0 = 0.f, a1 = 0.f, a2 = 0.f, a3 = 0.f;
        if (col < IFW) {
            const float* W = W_if + col;
#pragma unroll 4
            for (int k = 0; k < H; k += 4) {
                a0 = fmaf(s_h[k],     W[(size_t)(k)     * IFW], a0);
                a1 = fmaf(s_h[k + 1], W[(size_t)(k + 1) * IFW], a1);
                a2 = fmaf(s_h[k + 2], W[(size_t)(k + 2) * IFW], a2);
                a3 = fmaf(s_h[k + 3], W[(size_t)(k + 3) * IFW], a3);
            }
            g_iface[b][col] = (a0 + a1) + (a2 + a3) + b_if[col];
        } else {
            int c2 = col - IFW;
            const float* W = W_hid + c2;
#pragma unroll 4
            for (int k = 0; k < H; k += 4) {
                a0 = fmaf(s_h[k],     W[(size_t)(k)     * O_OUT], a0);
                a1 = fmaf(s_h[k + 1], W[(size_t)(k + 1) * O_OUT], a1);
                a2 = fmaf(s_h[k + 2], W[(size_t)(k + 2) * O_OUT], a2);
                a3 = fmaf(s_h[k + 3], W[(size_t)(k + 3) * O_OUT], a3);
            }
            g_outhid[b][c2] = (a0 + a1) + (a2 + a3) + b_hid[c2];
        }
    }
}

// ============ K4b: usage + alloc (rank-free log-sum) + cwexp ============
// grid (8 chunks, B), 256 threads; chunk owns 128 slots/rows
__global__ void __launch_bounds__(256, 1)
k4b_rank(const float* __restrict__ rw_prev, const float* __restrict__ ww_prev,
         const float* __restrict__ usage_prev, const float* __restrict__ mem_prev) {
    __shared__ float s_u[A];
    __shared__ float s_lu[A];
    __shared__ float s_kw[M];
    __shared__ float s_free[R];
    __shared__ float s_bw[1];
    __shared__ float s_red[8];
    int tid = threadIdx.x;
    int chunk = blockIdx.x, b = blockIdx.y;

    if (tid < R) s_free[tid] = sigf(g_iface[b][OFF_FREE + tid]);
    if (tid < M) s_kw[tid] = g_iface[b][OFF_KW + tid];
    if (tid == 0) s_bw[0] = oneplusf(g_iface[b][OFF_BETAW]);
    __syncthreads();

#pragma unroll
    for (int ii = 0; ii < 4; ii++) {
        int a = tid + ii * 256;
        float psi = 1.f;
#pragma unroll
        for (int r = 0; r < R; r++)
            psi *= (1.f - s_free[r] * rw_prev[(b * R + r) * A + a]);
        float u = usage_prev[b * A + a], w = ww_prev[b * A + a];
        float uv = (u + w - u * w) * psi;
        s_u[a] = uv;
        s_lu[a] = logf(uv);
    }
    __syncthreads();

    // alloc: 2 threads per slot; accumulate sum of logs over "lesser" elements
    {
        int slot = chunk * 128 + (tid >> 1);
        int half = tid & 1;
        float u = s_u[slot];
        float ls = 0.f;
        int base = half * 512;
#pragma unroll 8
        for (int i = 0; i < 512; i++) {
            int ia = base + i;
            float v = s_u[ia];
            bool less = (v < u) || (v == u && ia < slot);
            ls += less ? s_lu[ia] : 0.f;
        }
        ls += __shfl_xor_sync(0xffffffffu, ls, 1);
        if (half == 0) g_alloc[b][slot] = (1.f - u) * expf(ls);
    }

    // cwexp: 2 threads per row, each 32 floats (8 float4); logits <= beta_w
    float contrib = 0.f;
    {
        int row = chunk * 128 + (tid >> 1);
        int half = tid & 1;
        const float4* mrow =
            reinterpret_cast<const float4*>(mem_prev + ((size_t)(b * A + row)) * M) + half * 8;
        float d = 0.f, n = 0.f;
#pragma unroll
        for (int q = 0; q < 8; q++) {
            float4 v = mrow[q];
            int m0 = half * 32 + q * 4;
            d += v.x * s_kw[m0] + v.y * s_kw[m0 + 1] + v.z * s_kw[m0 + 2] + v.w * s_kw[m0 + 3];
            n += v.x * v.x + v.y * v.y + v.z * v.z + v.w * v.w;
        }
        d += __shfl_xor_sync(0xffffffffu, d, 1);
        n += __shfl_xor_sync(0xffffffffu, n, 1);
        if (half == 0) {
            float kn2 = 0.f;
#pragma unroll
            for (int m = 0; m < M; m++) { float v = s_kw[m]; kn2 = fmaf(v, v, kn2); }
            float bw = s_bw[0];
            float l = bw * d / (sqrtf(kn2) * sqrtf(n) + 1e-6f);
            float e = expf(l - bw);
            g_cwexp[b][row] = e;
            contrib = e;
        }
    }
    float csum = blockSum<256>(contrib, s_red);
    if (tid == 0) g_cwpart[b][chunk] = csum;
}

// ============ K57: ww (from precomputed alloc/cwexp) + mem write + c_r + link ====
// grid (16 stripes, B), 256 threads
__global__ void __launch_bounds__(256, 3)
k57_mem_link(const float* __restrict__ mem_prev, const float* __restrict__ link_prev,
             const float* __restrict__ rw_prev, const float* __restrict__ prec_prev) {
    __shared__ double s_pack[PACKN];          // 36 KB skewed
    __shared__ float  s_ww[A];
    __shared__ float  s_kr[R][M];
    __shared__ float  s_er[M], s_wv[M];
    __shared__ float  s_beta[R], s_kn[R];
    __shared__ float  s_red[8];
    int tid = threadIdx.x;                    // 256
    int stripe = blockIdx.x;                  // 16 stripes of 64 rows
    int b = blockIdx.y;
    int jbase = stripe * 64;

    // --- params ---
    {
        int r = tid >> 6, m = tid & 63;
        s_kr[r][m] = g_iface[b][OFF_KR + r * M + m];
        if (tid < M) s_er[tid] = sigf(g_iface[b][OFF_ERASE + tid]);
        else if (tid < 2 * M) s_wv[tid - M] = g_iface[b][OFF_WRITEV + (tid - M)];
    }
    if (tid < R) {
        s_beta[tid] = oneplusf(g_iface[b][OFF_BETAR + tid]);
    }

    // --- ww from precomputed alloc/cwexp (no cumprod) ---
    {
        float csum = 0.f;
#pragma unroll
        for (int c = 0; c < 8; c++) csum += g_cwpart[b][c];
        float inv = 1.f / csum;
        float ga = sigf(g_iface[b][OFF_GA]), gw = sigf(g_iface[b][OFF_GW]);
        float wwv[4];
#pragma unroll
        for (int ii = 0; ii < 4; ii++) {
            int a = tid + ii * 256;
            float alloc = g_alloc[b][a];
            float cwn = g_cwexp[b][a] * inv;
            wwv[ii] = gw * (ga * alloc + (1.f - ga) * cwn);
            s_ww[a] = wwv[ii];
        }
        if (stripe == 0) {
            float sS[R] = {0, 0, 0, 0}, sT[R] = {0, 0, 0, 0};
#pragma unroll
            for (int ii = 0; ii < 4; ii++) {
                int a = tid + ii * 256;
                g_ww[b][a] = wwv[ii];
                float pp = prec_prev[b * A + a];
#pragma unroll
                for (int r = 0; r < R; r++) {
                    float rw = rw_prev[(b * R + r) * A + a];
                    sS[r] = fmaf(pp, rw, sS[r]);
                    sT[r] = fmaf(wwv[ii], rw, sT[r]);
                }
            }
#pragma unroll
            for (int r = 0; r < R; r++) {
                float v = blockSum<256>(sS[r], s_red);
                if (tid == 0) g_S[b][r] = v;
                v = blockSum<256>(sT[r], s_red);
                if (tid == 0) g_T[b][r] = v;
            }
        }
    }
    __syncthreads();
    if (tid < R) {
        float s = 0.f;
#pragma unroll
        for (int m = 0; m < M; m++) { float v = s_kr[tid][m]; s = fmaf(v, v, s); }
        s_kn[tid] = sqrtf(s);
    }
    __syncthreads();

    // --- part 1: mem update + cr logits for rows [jbase, jbase+64) ---
    {
        int lane16 = tid & 15, m0 = lane16 * 4;
#pragma unroll
        for (int pass = 0; pass < 4; pass++) {
            int a = jbase + pass * 16 + (tid >> 4);
            float w = s_ww[a];
            float4 v = *reinterpret_cast<const float4*>(mem_prev + ((size_t)(b * A + a)) * M + m0);
            float n0 = v.x * (1.f - w * s_er[m0])     + w * s_wv[m0];
            float n1 = v.y * (1.f - w * s_er[m0 + 1]) + w * s_wv[m0 + 1];
            float n2 = v.z * (1.f - w * s_er[m0 + 2]) + w * s_wv[m0 + 2];
            float n3 = v.w * (1.f - w * s_er[m0 + 3]) + w * s_wv[m0 + 3];
            *reinterpret_cast<float4*>(&g_mem[b][a][m0]) = make_float4(n0, n1, n2, n3);
            float nn = n0 * n0 + n1 * n1 + n2 * n2 + n3 * n3;
            float d[R];
#pragma unroll
            for (int r = 0; r < R; r++)
                d[r] = n0 * s_kr[r][m0] + n1 * s_kr[r][m0 + 1] +
                       n2 * s_kr[r][m0 + 2] + n3 * s_kr[r][m0 + 3];
#pragma unroll
            for (int o = 8; o; o >>= 1) {
                nn += __shfl_xor_sync(0xffffffffu, nn, o);
#pragma unroll
                for (int r = 0; r < R; r++) d[r] += __shfl_xor_sync(0xffffffffu, d[r], o);
            }
            if (lane16 == 0) {
                float mn = sqrtf(nn);
#pragma unroll
                for (int r = 0; r < R; r++)
                    g_cr[b][r][a] = s_beta[r] * d[r] / (s_kn[r] * mn + 1e-6f);
            }
        }
    }

    // --- pack table (skewed layout) ---
    for (int a = tid; a < A; a += 256) {
        float w = s_ww[a];
        double* dst = s_pack + packIdx(a);
#pragma unroll
        for (int r = 0; r < R; r++) {
            float rw = rw_prev[(b * R + r) * A + a];
            dst[r] = pack2(rw, w * rw);
        }
    }
    __syncthreads();

    const float* Lp = link_prev + (size_t)b * A * A;

    // --- phase A: column partials (u,v); thread owns 4 cols, 64 rows ---
    {
        int col4 = 4 * tid;
        double uv[4][R];
#pragma unroll
        for (int c = 0; c < 4; c++)
#pragma unroll
            for (int r = 0; r < R; r++) uv[c][r] = 0.0;
#pragma unroll 4
        for (int j = 0; j < 64; j++) {
            int row = jbase + j;
            float4 val = *reinterpret_cast<const float4*>(Lp + (size_t)row * A + col4);
            const double* base = s_pack + packIdx(row);
            double2 pk01 = *reinterpret_cast<const double2*>(base);
            double2 pk23 = *reinterpret_cast<const double2*>(base + 2);
            double sx = splat2(val.x), sy = splat2(val.y);
            double sz = splat2(val.z), sw = splat2(val.w);
            fma2(uv[0][0], sx, pk01.x); fma2(uv[0][1], sx, pk01.y);
            fma2(uv[0][2], sx, pk23.x); fma2(uv[0][3], sx, pk23.y);
            fma2(uv[1][0], sy, pk01.x); fma2(uv[1][1], sy, pk01.y);
            fma2(uv[1][2], sy, pk23.x); fma2(uv[1][3], sy, pk23.y);
            fma2(uv[2][0], sz, pk01.x); fma2(uv[2][1], sz, pk01.y);
            fma2(uv[2][2], sz, pk23.x); fma2(uv[2][3], sz, pk23.y);
            fma2(uv[3][0], sw, pk01.x); fma2(uv[3][1], sw, pk01.y);
            fma2(uv[3][2], sw, pk23.x); fma2(uv[3][3], sw, pk23.y);
        }
#pragma unroll
        for (int r = 0; r < R; r++) {
            double2 st0; st0.x = uv[0][r]; st0.y = uv[1][r];
            double2 st1; st1.x = uv[2][r]; st1.y = uv[3][r];
            *reinterpret_cast<double2*>(&g_UVp[stripe][b][r][col4]) = st0;
            *reinterpret_cast<double2*>(&g_UVp[stripe][b][r][col4 + 2]) = st1;
        }
    }

    // --- phase B: row dots (p,q); warp-coherent, 2 rows/thread, skewed pack ---
    {
        int lane8 = tid & 7;
        int rowg = tid >> 3;               // 0..31
        int row0 = jbase + rowg;
        int row1 = jbase + rowg + 32;
        const float* Lr0 = Lp + (size_t)row0 * A;
        const float* Lr1 = Lp + (size_t)row1 * A;
        double pq0[R] = {0.0, 0.0, 0.0, 0.0};
        double pq1[R] = {0.0, 0.0, 0.0, 0.0};
#pragma unroll 2
        for (int step = 0; step < 32; step++) {
            int col = step * 32 + lane8 * 4;
            float4 v0 = *reinterpret_cast<const float4*>(Lr0 + col);
            float4 v1 = *reinterpret_cast<const float4*>(Lr1 + col);
            const double* base = s_pack + 18 * (col >> 2);
            double2 p0 = *reinterpret_cast<const double2*>(base + 0);
            double2 p1 = *reinterpret_cast<const double2*>(base + 2);
            double2 p2 = *reinterpret_cast<const double2*>(base + 4);
            double2 p3 = *reinterpret_cast<const double2*>(base + 6);
            double2 p4 = *reinterpret_cast<const double2*>(base + 8);
            double2 p5 = *reinterpret_cast<const double2*>(base + 10);
            double2 p6 = *reinterpret_cast<const double2*>(base + 12);
            double2 p7 = *reinterpret_cast<const double2*>(base + 14);
            double s;
            s = splat2(v0.x); fma2(pq0[0], s, p0.x); fma2(pq0[1], s, p0.y);
                              fma2(pq0[2], s, p1.x); fma2(pq0[3], s, p1.y);
            s = splat2(v0.y); fma2(pq0[0], s, p2.x); fma2(pq0[1], s, p2.y);
                              fma2(pq0[2], s, p3.x); fma2(pq0[3], s, p3.y);
            s = splat2(v0.z); fma2(pq0[0], s, p4.x); fma2(pq0[1], s, p4.y);
                              fma2(pq0[2], s, p5.x); fma2(pq0[3], s, p5.y);
            s = splat2(v0.w); fma2(pq0[0], s, p6.x); fma2(pq0[1], s, p6.y);
                              fma2(pq0[2], s, p7.x); fma2(pq0[3], s, p7.y);
            s = splat2(v1.x); fma2(pq1[0], s, p0.x); fma2(pq1[1], s, p0.y);
                              fma2(pq1[2], s, p1.x); fma2(pq1[3], s, p1.y);
            s = splat2(v1.y); fma2(pq1[0], s, p2.x); fma2(pq1[1], s, p2.y);
                              fma2(pq1[2], s, p3.x); fma2(pq1[3], s, p3.y);
            s = splat2(v1.z); fma2(pq1[0], s, p4.x); fma2(pq1[1], s, p4.y);
                              fma2(pq1[2], s, p5.x); fma2(pq1[3], s, p5.y);
            s = splat2(v1.w); fma2(pq1[0], s, p6.x); fma2(pq1[1], s, p6.y);
                              fma2(pq1[2], s, p7.x); fma2(pq1[3], s, p7.y);
        }
#pragma unroll
        for (int r = 0; r < R; r++) {
            pq0[r] = add2(pq0[r], __shfl_xor_sync(0xffffffffu, pq0[r], 1));
            pq0[r] = add2(pq0[r], __shfl_xor_sync(0xffffffffu, pq0[r], 2));
            pq0[r] = add2(pq0[r], __shfl_xor_sync(0xffffffffu, pq0[r], 4));
            pq1[r] = add2(pq1[r], __shfl_xor_sync(0xffffffffu, pq1[r], 1));
            pq1[r] = add2(pq1[r], __shfl_xor_sync(0xffffffffu, pq1[r], 2));
            pq1[r] = add2(pq1[r], __shfl_xor_sync(0xffffffffu, pq1[r], 4));
        }
        if (lane8 == 0) {
#pragma unroll
            for (int r = 0; r < R; r++) {
                g_PQ[b][r][row0] = pq0[r];
                g_PQ[b][r][row1] = pq1[r];
            }
        }
    }
}

// ============ K8: UV reduce + cr softmax + read weights + rv GEMV + output ====
// 1024 threads per block (2x warps for latency hiding at 16 blocks)
__global__ void __launch_bounds__(1024, 1)
k8_read_out(const float* __restrict__ rw_prev, const float* __restrict__ prec_prev,
            const float* __restrict__ W_rd, const float* __restrict__ b_rd,
            float* __restrict__ out) {
    int b = blockIdx.x;
    int tid = threadIdx.x;  // 1024
    __shared__ float s_wr[R][A];        // 16 KB
    __shared__ float s_racc[32][R][M];  // 32 KB
    __shared__ float s_rv[R * M];
    __shared__ float s_out[4][O_OUT];   // 4 KB
    __shared__ float s_pi[R][3];
    __shared__ float s_red[32];

    if (tid < R) {
        float l0 = g_iface[b][OFF_PI + tid * 3 + 0];
        float l1 = g_iface[b][OFF_PI + tid * 3 + 1];
        float l2 = g_iface[b][OFF_PI + tid * 3 + 2];
        float mx = fmaxf(l0, fmaxf(l1, l2));
        float e0 = __expf(l0 - mx), e1 = __expf(l1 - mx), e2 = __expf(l2 - mx);
        float inv = 1.f / (e0 + e1 + e2);
        s_pi[tid][0] = e0 * inv; s_pi[tid][1] = e1 * inv; s_pi[tid][2] = e2 * inv;
    }

#pragma unroll
    for (int r = 0; r < R; r++) {
        float l = g_cr[b][r][tid];
        float mx = blockMax<1024>(l, s_red);
        float e = __expf(l - mx);
        float s = blockSum<1024>(e, s_red);
        s_wr[r][tid] = e / s;
    }
    __syncthreads();

    {
        int a = tid;
        float ww = g_ww[b][a];
        float pp = prec_prev[b * A + a];
#pragma unroll
        for (int r = 0; r < R; r++) {
            float rw = rw_prev[(b * R + r) * A + a];
            float2 PQ = unpack2(g_PQ[b][r][a]);
            double uvs = g_UVp[0][b][r][a];
#pragma unroll
            for (int s16 = 1; s16 < 16; s16++) uvs = add2(uvs, g_UVp[s16][b][r][a]);
            float2 UV = unpack2(uvs);
            float Sr = g_S[b][r], Tr = g_T[b][r];
            float fwd = (1.f - ww) * PQ.x - PQ.y + ww * (Sr - pp * rw);
            float bwd = (1.f - ww) * UV.x - UV.y + pp * (Tr - ww * rw);
            float cr = s_wr[r][a];
            s_wr[r][a] = s_pi[r][0] * bwd + s_pi[r][1] * cr + s_pi[r][2] * fwd;
        }
    }
    __syncthreads();

    {
        int w = tid >> 5, lane = tid & 31;   // 32 warps
        float acc[2][R] = {{0, 0, 0, 0}, {0, 0, 0, 0}};
#pragma unroll 4
        for (int i = 0; i < 32; i++) {
            int a = i * 32 + w;
            float m0 = g_mem[b][a][lane];
            float m1 = g_mem[b][a][lane + 32];
#pragma unroll
            for (int r = 0; r < R; r++) {
                float wr = s_wr[r][a];
                acc[0][r] = fmaf(wr, m0, acc[0][r]);
                acc[1][r] = fmaf(wr, m1, acc[1][r]);
            }
        }
#pragma unroll
        for (int r = 0; r < R; r++) {
            s_racc[w][r][lane] = acc[0][r];
            s_racc[w][r][lane + 32] = acc[1][r];
        }
    }
    __syncthreads();
    if (tid < R * M) {
        float s = 0.f;
#pragma unroll
        for (int w = 0; w < 32; w++) s += s_racc[w][tid >> 6][tid & 63];
        s_rv[tid] = s;
    }
    __syncthreads();

    {
        int quarter = tid >> 8, col = tid & 255;
        float acc = 0.f;
        const float* W = W_rd + (size_t)quarter * 64 * O_OUT + col;
#pragma unroll 8
        for (int j = 0; j < 64; j++)
            acc = fmaf(s_rv[quarter * 64 + j], W[(size_t)j * O_OUT], acc);
        s_out[quarter][col] = acc;
    }
    __syncthreads();
    if (tid < O_OUT) {
        out[b * O_OUT + tid] = (s_out[0][tid] + s_out[1][tid]) + (s_out[2][tid] + s_out[3][tid]) +
                               g_outhid[b][tid] + b_rd[tid];
    }
}

// ----------------- launch -----------------
extern "C" void kernel_launch(void* const* d_in, const int* in_sizes, int n_in,
                              void* d_out, int out_size) {
    (void)in_sizes; (void)n_in; (void)out_size;
    const float* x          = (const float*)d_in[0];
    const float* h_prev     = (const float*)d_in[1];
    const float* c_prev     = (const float*)d_in[2];
    const float* mem_prev   = (const float*)d_in[3];
    const float* rw_prev    = (const float*)d_in[4];
    const float* ww_prev    = (const float*)d_in[5];
    const float* usage_prev = (const float*)d_in[6];
    const float* prec_prev  = (const float*)d_in[7];
    const float* link_prev  = (const float*)d_in[8];
    const float* rv_prev    = (const float*)d_in[9];
    const float* Wx         = (const float*)d_in[10];
    const float* Wh         = (const float*)d_in[11];
    const float* b_lstm     = (const float*)d_in[12];
    const float* W_hid      = (const float*)d_in[13];
    const float* b_hid      = (const float*)d_in[14];
    const float* W_if       = (const float*)d_in[15];
    const float* b_if       = (const float*)d_in[16];
    const float* W_rd       = (const float*)d_in[17];
    const float* b_rd       = (const float*)d_in[18];
    float* out = (float*)d_out;

    k1_zpart<<<dim3(4, 32), 256>>>(x, h_prev, rv_prev, Wx, Wh);
    k23_lstm_iface<<<dim3(2, B), 736>>>(c_prev, b_lstm, W_if, W_hid, b_if, b_hid);
    k4b_rank<<<dim3(8, B), 256>>>(rw_prev, ww_prev, usage_prev, mem_prev);
    k57_mem_link<<<dim3(16, B), 256>>>(mem_prev, link_prev, rw_prev, prec_prev);
    k8_read_out<<<B, 1024>>>(rw_prev, prec_prev, W_rd, b_rd, out);
}

// round 17
// speedup vs baseline: 1.4472x; 1.4472x over previous
#include <cuda_runtime.h>
#include <math.h>

#define B 16
#define I_IN 256
#define H 512
#define O_OUT 256
#define A 1024
#define M 64
#define R 4
#define IFW 471
#define N4H 2048
#define NCOLS3 (IFW + O_OUT)   // 727

// interface offsets
#define OFF_KR     0
#define OFF_BETAR  256
#define OFF_KW     260
#define OFF_BETAW  324
#define OFF_ERASE  325
#define OFF_WRITEV 389
#define OFF_FREE   453
#define OFF_GA     457
#define OFF_GW     458
#define OFF_PI     459

// skewed pack index: groups of 16 doubles padded to 18 (conflict-free for
// lane-stride-144B patterns)
#define PACKN (18 * 256)
__device__ __forceinline__ int packIdx(int a) { return 18 * (a >> 2) + 4 * (a & 3); }

// ----------------- device scratch -----------------
__device__ float  g_zpart[32][B][N4H];
__device__ float  g_iface[B][IFW];
__device__ float  g_outhid[B][O_OUT];
__device__ float  g_usage[B][A];
__device__ int    g_rank[B][A];
__device__ float  g_cwlog[B][A];
__device__ float  g_ww[B][A];
__device__ float  g_S[B][R];
__device__ float  g_T[B][R];
__device__ float  g_mem[B][A][M];
__device__ float  g_cr[B][R][A];
__device__ double g_PQ[B][R][A];        // packed (p,q)
__device__ double g_UVp[8][B][R][A];    // packed (u,v) partials per stripe

__device__ __forceinline__ float sigf(float x) { return 1.f / (1.f + __expf(-x)); }
__device__ __forceinline__ float oneplusf(float x) {
    return 1.f + (x > 20.f ? x : log1pf(__expf(x)));
}

// packed f32x2 helpers (double as bit-carrier)
__device__ __forceinline__ double pack2(float lo, float hi) {
    double d; asm("mov.b64 %0, {%1,%2};" : "=d"(d) : "f"(lo), "f"(hi)); return d;
}
__device__ __forceinline__ double splat2(float v) {
    double d; asm("mov.b64 %0, {%1,%1};" : "=d"(d) : "f"(v)); return d;
}
__device__ __forceinline__ void fma2(double& acc, double a, double b) {
    asm("fma.rn.f32x2 %0, %1, %2, %3;" : "=d"(acc) : "d"(a), "d"(b), "d"(acc));
}
__device__ __forceinline__ double add2(double a, double b) {
    double d; asm("add.rn.f32x2 %0, %1, %2;" : "=d"(d) : "d"(a), "d"(b)); return d;
}
__device__ __forceinline__ float2 unpack2(double d) {
    float2 f;
    asm("mov.b64 {%0,%1}, %2;" : "=f"(f.x), "=f"(f.y) : "l"(__double_as_longlong(d)));
    return f;
}

template <int NT>
__device__ __forceinline__ float blockSum(float v, float* s_red) {
    int lane = threadIdx.x & 31, w = threadIdx.x >> 5;
#pragma unroll
    for (int o = 16; o; o >>= 1) v += __shfl_down_sync(0xffffffffu, v, o);
    if (lane == 0) s_red[w] = v;
    __syncthreads();
    if (w == 0) {
        float x = (lane < NT / 32) ? s_red[lane] : 0.f;
#pragma unroll
        for (int o = 16; o; o >>= 1) x += __shfl_down_sync(0xffffffffu, x, o);
        if (lane == 0) s_red[0] = x;
    }
    __syncthreads();
    float res = s_red[0];
    __syncthreads();
    return res;
}
template <int NT>
__device__ __forceinline__ float blockMax(float v, float* s_red) {
    int lane = threadIdx.x & 31, w = threadIdx.x >> 5;
#pragma unroll
    for (int o = 16; o; o >>= 1) v = fmaxf(v, __shfl_down_sync(0xffffffffu, v, o));
    if (lane == 0) s_red[w] = v;
    __syncthreads();
    if (w == 0) {
        float x = (lane < NT / 32) ? s_red[lane] : -1e30f;
#pragma unroll
        for (int o = 16; o; o >>= 1) x = fmaxf(x, __shfl_down_sync(0xffffffffu, x, o));
        if (lane == 0) s_red[0] = x;
    }
    __syncthreads();
    float res = s_red[0];
    __syncthreads();
    return res;
}

// ============ K1: z GEMM, k-split 32 chunks of 32, packed f32x2 (128 blocks) ============
__global__ void __launch_bounds__(256, 1)
k1_zpart(const float* __restrict__ x, const float* __restrict__ h_prev,
         const float* __restrict__ rv_prev, const float* __restrict__ Wx,
         const float* __restrict__ Wh) {
    __shared__ double s_in2[B][32];
    int tid = threadIdx.x;
    int ntile = blockIdx.x;
    int kc = blockIdx.y;
    int kbase = kc * 32;
    for (int idx = tid; idx < B * 32; idx += 256) {
        int b = idx >> 5, kl = idx & 31;
        int kk = kbase + kl;
        float v;
        if (kk < 256) v = x[b * I_IN + kk];
        else if (kk < 512) v = rv_prev[b * 256 + (kk - 256)];
        else v = h_prev[b * H + (kk - 512)];
        s_in2[b][kl] = splat2(v);
    }
    __syncthreads();
    int n0 = ntile * 512 + tid * 2;
    const float* Wbase = (kbase < 512) ? (Wx + (size_t)kbase * N4H)
                                       : (Wh + (size_t)(kbase - 512) * N4H);
    const char* Wp = (const char*)(Wbase + n0);
    double acc2[B];
#pragma unroll
    for (int b = 0; b < B; b++) acc2[b] = 0.0;
#pragma unroll 4
    for (int kl = 0; kl < 32; kl++) {
        double w2 = *(const double*)(Wp + (size_t)kl * (N4H * 4));
#pragma unroll
        for (int b = 0; b < B; b++) fma2(acc2[b], s_in2[b][kl], w2);
    }
#pragma unroll
    for (int b = 0; b < B; b++)
        *(double*)&g_zpart[kc][b][n0] = acc2[b];
}

// ============ K23: LSTM (z reduce) + iface/out_hidden GEMM, grid (2, B) ============
__global__ void __launch_bounds__(736, 1)
k23_lstm_iface(const float* __restrict__ c_prev, const float* __restrict__ b_lstm,
               const float* __restrict__ W_if, const float* __restrict__ W_hid,
               const float* __restrict__ b_if, const float* __restrict__ b_hid) {
    __shared__ float s_h[H];
    int tid = threadIdx.x;
    int half = blockIdx.x;
    int b = blockIdx.y;

    if (tid < H) {
        float zv[4];
#pragma unroll
        for (int g = 0; g < 4; g++) {
            int n = g * H + tid;
            float s = b_lstm[n];
#pragma unroll
            for (int kc = 0; kc < 32; kc++) s += g_zpart[kc][b][n];
            zv[g] = s;
        }
        float c = sigf(zv[1]) * c_prev[b * H + tid] + sigf(zv[0]) * tanhf(zv[2]);
        s_h[tid] = sigf(zv[3]) * tanhf(c);
    }
    __syncthreads();

    int col = half * 368 + tid;
    if (tid < 368 && col < NCOLS3) {
        float a0 = 0.f, a1 = 0.f, a2 = 0.f, a3 = 0.f;
        if (col < IFW) {
            const float* W = W_if + col;
#pragma unroll 4
            for (int k = 0; k < H; k += 4) {
                a0 = fmaf(s_h[k],     W[(size_t)(k)     * IFW], a0);
                a1 = fmaf(s_h[k + 1], W[(size_t)(k + 1) * IFW], a1);
                a2 = fmaf(s_h[k + 2], W[(size_t)(k + 2) * IFW], a2);
                a3 = fmaf(s_h[k + 3], W[(size_t)(k + 3) * IFW], a3);
            }
            g_iface[b][col] = (a0 + a1) + (a2 + a3) + b_if[col];
        } else {
            int c2 = col - IFW;
            const float* W = W_hid + c2;
#pragma unroll 4
            for (int k = 0; k < H; k += 4) {
                a0 = fmaf(s_h[k],     W[(size_t)(k)     * O_OUT], a0);
                a1 = fmaf(s_h[k + 1], W[(size_t)(k + 1) * O_OUT], a1);
                a2 = fmaf(s_h[k + 2], W[(size_t)(k + 2) * O_OUT], a2);
                a3 = fmaf(s_h[k + 3], W[(size_t)(k + 3) * O_OUT], a3);
            }
            g_outhid[b][c2] = (a0 + a1) + (a2 + a3) + b_hid[c2];
        }
    }
}

// ============ K4b: usage (in-block) + rank (broadcast scan) + cwlog ============
__global__ void __launch_bounds__(256, 1)
k4b_rank(const float* __restrict__ rw_prev, const float* __restrict__ ww_prev,
         const float* __restrict__ usage_prev, const float* __restrict__ mem_prev) {
    __shared__ float s_u[A];
    __shared__ float s_kw[M];
    __shared__ float s_free[R];
    __shared__ float s_bw[1];
    int tid = threadIdx.x;
    int chunk = blockIdx.x, b = blockIdx.y;

    if (tid < R) s_free[tid] = sigf(g_iface[b][OFF_FREE + tid]);
    if (tid < M) s_kw[tid] = g_iface[b][OFF_KW + tid];
    if (tid == 0) s_bw[0] = oneplusf(g_iface[b][OFF_BETAW]);
    __syncthreads();

#pragma unroll
    for (int ii = 0; ii < 4; ii++) {
        int a = tid + ii * 256;
        float psi = 1.f;
#pragma unroll
        for (int r = 0; r < R; r++)
            psi *= (1.f - s_free[r] * rw_prev[(b * R + r) * A + a]);
        float u = usage_prev[b * A + a], w = ww_prev[b * A + a];
        s_u[a] = (u + w - u * w) * psi;
    }
    __syncthreads();
    if (tid < 128) g_usage[b][chunk * 128 + tid] = s_u[chunk * 128 + tid];

    {
        int slot = chunk * 128 + (tid >> 1);
        int half = tid & 1;
        float u = s_u[slot];
        int cnt = 0;
        int base = half * 512;
#pragma unroll 8
        for (int i = 0; i < 512; i++) {
            float v = s_u[base + i];
            int ia = base + i;
            cnt += (v < u) || (v == u && ia < slot);
        }
        cnt += __shfl_xor_sync(0xffffffffu, cnt, 1);
        if (half == 0) g_rank[b][slot] = cnt;
    }

    {
        int row = chunk * 128 + (tid >> 1);
        int half = tid & 1;
        const float4* mrow =
            reinterpret_cast<const float4*>(mem_prev + ((size_t)(b * A + row)) * M) + half * 8;
        float d = 0.f, n = 0.f;
#pragma unroll
        for (int q = 0; q < 8; q++) {
            float4 v = mrow[q];
            int m0 = half * 32 + q * 4;
            d += v.x * s_kw[m0] + v.y * s_kw[m0 + 1] + v.z * s_kw[m0 + 2] + v.w * s_kw[m0 + 3];
            n += v.x * v.x + v.y * v.y + v.z * v.z + v.w * v.w;
        }
        d += __shfl_xor_sync(0xffffffffu, d, 1);
        n += __shfl_xor_sync(0xffffffffu, n, 1);
        if (half == 0) {
            float kn2 = 0.f;
#pragma unroll
            for (int m = 0; m < M; m++) { float v = s_kw[m]; kn2 = fmaf(v, v, kn2); }
            g_cwlog[b][row] = s_bw[0] * d / (sqrtf(kn2) * sqrtf(n) + 1e-6f);
        }
    }
}

// ============ K57: alloc/ww (inline) + mem write + c_r + link pass (prefetched) ====
__global__ void __launch_bounds__(512, 1)
k57_mem_link(const float* __restrict__ mem_prev, const float* __restrict__ link_prev,
             const float* __restrict__ rw_prev, const float* __restrict__ prec_prev) {
    __shared__ double s_pack[PACKN];          // 36 KB skewed; front overlaid by cumprod scratch
    __shared__ float  s_ww[A];
    __shared__ float  s_kr[R][M];
    __shared__ float  s_er[M], s_wv[M];
    __shared__ float  s_beta[R], s_kn[R];
    __shared__ float  s_red[16];
    int tid = threadIdx.x;                    // 512
    int stripe = blockIdx.x;                  // 8 stripes of 128 rows
    int b = blockIdx.y;
    int jbase = stripe * 128;

    float* s_sorted = (float*)s_pack;         // [A]
    float* s_tmp = ((float*)s_pack) + A;      // [A]

    // --- params ---
    if (tid < 256) {
        int r = tid >> 6, m = tid & 63;
        s_kr[r][m] = g_iface[b][OFF_KR + r * M + m];
    } else if (tid < 256 + M) {
        s_er[tid - 256] = sigf(g_iface[b][OFF_ERASE + (tid - 256)]);
    } else if (tid < 256 + 2 * M) {
        s_wv[tid - 256 - M] = g_iface[b][OFF_WRITEV + (tid - 256 - M)];
    }
    __syncthreads();
    if (tid < R) {
        s_beta[tid] = oneplusf(g_iface[b][OFF_BETAR + tid]);
        float s = 0.f;
#pragma unroll
        for (int m = 0; m < M; m++) { float v = s_kr[tid][m]; s = fmaf(v, v, s); }
        s_kn[tid] = sqrtf(s);
    }

    // --- alloc + ww (redundant per block) ---
    float u0 = g_usage[b][tid], u1 = g_usage[b][tid + 512];
    int r0 = g_rank[b][tid], r1 = g_rank[b][tid + 512];
    s_sorted[r0] = u0;
    s_sorted[r1] = u1;
    __syncthreads();
    {
        float* src = s_sorted;
        float* dst = s_tmp;
        for (int off = 1; off < A; off <<= 1) {
            for (int i = tid; i < A; i += 512)
                dst[i] = (i >= off) ? src[i - off] * src[i] : src[i];
            __syncthreads();
            float* t = src; src = dst; dst = t;
        }
        float alloc0 = (1.f - u0) * (r0 == 0 ? 1.f : src[r0 - 1]);
        float alloc1 = (1.f - u1) * (r1 == 0 ? 1.f : src[r1 - 1]);

        float l0 = g_cwlog[b][tid], l1 = g_cwlog[b][tid + 512];
        float mx = blockMax<512>(fmaxf(l0, l1), s_red);
        float e0 = __expf(l0 - mx), e1 = __expf(l1 - mx);
        float ssum = blockSum<512>(e0 + e1, s_red);
        float inv = 1.f / ssum;

        float ga = sigf(g_iface[b][OFF_GA]), gw = sigf(g_iface[b][OFF_GW]);
        float wwv0 = gw * (ga * alloc0 + (1.f - ga) * e0 * inv);
        float wwv1 = gw * (ga * alloc1 + (1.f - ga) * e1 * inv);
        s_ww[tid] = wwv0;
        s_ww[tid + 512] = wwv1;

        if (stripe == 0) {
            g_ww[b][tid] = wwv0;
            g_ww[b][tid + 512] = wwv1;
            float pp0 = prec_prev[b * A + tid], pp1 = prec_prev[b * A + tid + 512];
            float sS[R], sT[R];
#pragma unroll
            for (int r = 0; r < R; r++) {
                float rw0 = rw_prev[(b * R + r) * A + tid];
                float rw1 = rw_prev[(b * R + r) * A + tid + 512];
                sS[r] = fmaf(pp0, rw0, pp1 * rw1);
                sT[r] = fmaf(wwv0, rw0, wwv1 * rw1);
            }
#pragma unroll
            for (int r = 0; r < R; r++) {
                float v = blockSum<512>(sS[r], s_red);
                if (tid == 0) g_S[b][r] = v;
                v = blockSum<512>(sT[r], s_red);
                if (tid == 0) g_T[b][r] = v;
            }
        }
    }
    __syncthreads();

    // --- part 1: mem update + cr logits for rows [jbase, jbase+128) ---
    {
        int lane16 = tid & 15, m0 = lane16 * 4;
#pragma unroll
        for (int pass = 0; pass < 4; pass++) {
            int a = jbase + pass * 32 + (tid >> 4);
            float w = s_ww[a];
            float4 v = *reinterpret_cast<const float4*>(mem_prev + ((size_t)(b * A + a)) * M + m0);
            float n0 = v.x * (1.f - w * s_er[m0])     + w * s_wv[m0];
            float n1 = v.y * (1.f - w * s_er[m0 + 1]) + w * s_wv[m0 + 1];
            float n2 = v.z * (1.f - w * s_er[m0 + 2]) + w * s_wv[m0 + 2];
            float n3 = v.w * (1.f - w * s_er[m0 + 3]) + w * s_wv[m0 + 3];
            *reinterpret_cast<float4*>(&g_mem[b][a][m0]) = make_float4(n0, n1, n2, n3);
            float nn = n0 * n0 + n1 * n1 + n2 * n2 + n3 * n3;
            float d[R];
#pragma unroll
            for (int r = 0; r < R; r++)
                d[r] = n0 * s_kr[r][m0] + n1 * s_kr[r][m0 + 1] +
                       n2 * s_kr[r][m0 + 2] + n3 * s_kr[r][m0 + 3];
#pragma unroll
            for (int o = 8; o; o >>= 1) {
                nn += __shfl_xor_sync(0xffffffffu, nn, o);
#pragma unroll
                for (int r = 0; r < R; r++) d[r] += __shfl_xor_sync(0xffffffffu, d[r], o);
            }
            if (lane16 == 0) {
                float mn = sqrtf(nn);
#pragma unroll
                for (int r = 0; r < R; r++)
                    g_cr[b][r][a] = s_beta[r] * d[r] / (s_kn[r] * mn + 1e-6f);
            }
        }
    }
    __syncthreads();   // alloc/part1 reads done before pack overwrites scratch

    // --- pack table (skewed layout) ---
    for (int a = tid; a < A; a += 512) {
        float w = s_ww[a];
        double* dst = s_pack + packIdx(a);
#pragma unroll
        for (int r = 0; r < R; r++) {
            float rw = rw_prev[(b * R + r) * A + a];
            dst[r] = pack2(rw, w * rw);
        }
    }
    __syncthreads();

    const float* Lp = link_prev + (size_t)b * A * A;

    // --- phase A: column partials (u,v); thread owns 2 cols, 128 rows, MLP-8 prefetch ---
    {
        int col2 = 2 * tid;
        double uv0[R], uv1[R];
#pragma unroll
        for (int r = 0; r < R; r++) { uv0[r] = 0.0; uv1[r] = 0.0; }
        float2 buf[8];
#pragma unroll
        for (int p = 0; p < 8; p++)
            buf[p] = *reinterpret_cast<const float2*>(Lp + (size_t)(jbase + p) * A + col2);
#pragma unroll 8
        for (int j = 0; j < 128; j++) {
            float2 val = buf[j & 7];
            if (j < 120)
                buf[j & 7] =
                    *reinterpret_cast<const float2*>(Lp + (size_t)(jbase + j + 8) * A + col2);
            const double* base = s_pack + packIdx(jbase + j);
            double2 pk01 = *reinterpret_cast<const double2*>(base);
            double2 pk23 = *reinterpret_cast<const double2*>(base + 2);
            double sx = splat2(val.x), sy = splat2(val.y);
            fma2(uv0[0], sx, pk01.x); fma2(uv0[1], sx, pk01.y);
            fma2(uv0[2], sx, pk23.x); fma2(uv0[3], sx, pk23.y);
            fma2(uv1[0], sy, pk01.x); fma2(uv1[1], sy, pk01.y);
            fma2(uv1[2], sy, pk23.x); fma2(uv1[3], sy, pk23.y);
        }
#pragma unroll
        for (int r = 0; r < R; r++) {
            double2 st; st.x = uv0[r]; st.y = uv1[r];
            *reinterpret_cast<double2*>(&g_UVp[stripe][b][r][col2]) = st;
        }
    }

    // --- phase B: row dots (p,q); warp-coherent, 2 rows/thread, MLP-8 prefetch ---
    {
        int lane8 = tid & 7;
        int rowg = tid >> 3;               // 0..63
        int row0 = jbase + rowg;
        int row1 = jbase + rowg + 64;
        const float* Lr0 = Lp + (size_t)row0 * A;
        const float* Lr1 = Lp + (size_t)row1 * A;
        double pq0[R] = {0.0, 0.0, 0.0, 0.0};
        double pq1[R] = {0.0, 0.0, 0.0, 0.0};
        float4 b0[4], b1[4];
#pragma unroll
        for (int p = 0; p < 4; p++) {
            int col = p * 32 + lane8 * 4;
            b0[p] = *reinterpret_cast<const float4*>(Lr0 + col);
            b1[p] = *reinterpret_cast<const float4*>(Lr1 + col);
        }
#pragma unroll 4
        for (int step = 0; step < 32; step++) {
            float4 v0 = b0[step & 3];
            float4 v1 = b1[step & 3];
            if (step < 28) {
                int col = (step + 4) * 32 + lane8 * 4;
                b0[step & 3] = *reinterpret_cast<const float4*>(Lr0 + col);
                b1[step & 3] = *reinterpret_cast<const float4*>(Lr1 + col);
            }
            int colc = step * 32 + lane8 * 4;
            const double* base = s_pack + 18 * (colc >> 2);
            double2 p0 = *reinterpret_cast<const double2*>(base + 0);
            double2 p1 = *reinterpret_cast<const double2*>(base + 2);
            double2 p2 = *reinterpret_cast<const double2*>(base + 4);
            double2 p3 = *reinterpret_cast<const double2*>(base + 6);
            double2 p4 = *reinterpret_cast<const double2*>(base + 8);
            double2 p5 = *reinterpret_cast<const double2*>(base + 10);
            double2 p6 = *reinterpret_cast<const double2*>(base + 12);
            double2 p7 = *reinterpret_cast<const double2*>(base + 14);
            double s;
            s = splat2(v0.x); fma2(pq0[0], s, p0.x); fma2(pq0[1], s, p0.y);
                              fma2(pq0[2], s, p1.x); fma2(pq0[3], s, p1.y);
            s = splat2(v0.y); fma2(pq0[0], s, p2.x); fma2(pq0[1], s, p2.y);
                              fma2(pq0[2], s, p3.x); fma2(pq0[3], s, p3.y);
            s = splat2(v0.z); fma2(pq0[0], s, p4.x); fma2(pq0[1], s, p4.y);
                              fma2(pq0[2], s, p5.x); fma2(pq0[3], s, p5.y);
            s = splat2(v0.w); fma2(pq0[0], s, p6.x); fma2(pq0[1], s, p6.y);
                              fma2(pq0[2], s, p7.x); fma2(pq0[3], s, p7.y);
            s = splat2(v1.x); fma2(pq1[0], s, p0.x); fma2(pq1[1], s, p0.y);
                              fma2(pq1[2], s, p1.x); fma2(pq1[3], s, p1.y);
            s = splat2(v1.y); fma2(pq1[0], s, p2.x); fma2(pq1[1], s, p2.y);
                              fma2(pq1[2], s, p3.x); fma2(pq1[3], s, p3.y);
            s = splat2(v1.z); fma2(pq1[0], s, p4.x); fma2(pq1[1], s, p4.y);
                              fma2(pq1[2], s, p5.x); fma2(pq1[3], s, p5.y);
            s = splat2(v1.w); fma2(pq1[0], s, p6.x); fma2(pq1[1], s, p6.y);
                              fma2(pq1[2], s, p7.x); fma2(pq1[3], s, p7.y);
        }
#pragma unroll
        for (int r = 0; r < R; r++) {
            pq0[r] = add2(pq0[r], __shfl_xor_sync(0xffffffffu, pq0[r], 1));
            pq0[r] = add2(pq0[r], __shfl_xor_sync(0xffffffffu, pq0[r], 2));
            pq0[r] = add2(pq0[r], __shfl_xor_sync(0xffffffffu, pq0[r], 4));
            pq1[r] = add2(pq1[r], __shfl_xor_sync(0xffffffffu, pq1[r], 1));
            pq1[r] = add2(pq1[r], __shfl_xor_sync(0xffffffffu, pq1[r], 2));
            pq1[r] = add2(pq1[r], __shfl_xor_sync(0xffffffffu, pq1[r], 4));
        }
        if (lane8 == 0) {
#pragma unroll
            for (int r = 0; r < R; r++) {
                g_PQ[b][r][row0] = pq0[r];
                g_PQ[b][r][row1] = pq1[r];
            }
        }
    }
}

// ============ K8: UV reduce + cr softmax + read weights + rv GEMV + output ====
__global__ void __launch_bounds__(512, 1)
k8_read_out(const float* __restrict__ rw_prev, const float* __restrict__ prec_prev,
            const float* __restrict__ W_rd, const float* __restrict__ b_rd,
            float* __restrict__ out) {
    int b = blockIdx.x;
    int tid = threadIdx.x;  // 512
    __shared__ float s_wr[R][A];
    __shared__ float s_racc[16][R][M];
    __shared__ float s_rv[R * M];
    __shared__ float s_out[2][O_OUT];
    __shared__ float s_pi[R][3];
    __shared__ float s_red[16];

    if (tid < R) {
        float l0 = g_iface[b][OFF_PI + tid * 3 + 0];
        float l1 = g_iface[b][OFF_PI + tid * 3 + 1];
        float l2 = g_iface[b][OFF_PI + tid * 3 + 2];
        float mx = fmaxf(l0, fmaxf(l1, l2));
        float e0 = __expf(l0 - mx), e1 = __expf(l1 - mx), e2 = __expf(l2 - mx);
        float inv = 1.f / (e0 + e1 + e2);
        s_pi[tid][0] = e0 * inv; s_pi[tid][1] = e1 * inv; s_pi[tid][2] = e2 * inv;
    }

#pragma unroll
    for (int r = 0; r < R; r++) {
        float l0 = g_cr[b][r][tid], l1 = g_cr[b][r][tid + 512];
        float mx = blockMax<512>(fmaxf(l0, l1), s_red);
        float e0 = __expf(l0 - mx), e1 = __expf(l1 - mx);
        float s = blockSum<512>(e0 + e1, s_red);
        float inv = 1.f / s;
        s_wr[r][tid] = e0 * inv;
        s_wr[r][tid + 512] = e1 * inv;
    }
    __syncthreads();

    for (int ii = 0; ii < 2; ii++) {
        int a = tid + ii * 512;
        float ww = g_ww[b][a];
        float pp = prec_prev[b * A + a];
#pragma unroll
        for (int r = 0; r < R; r++) {
            float rw = rw_prev[(b * R + r) * A + a];
            float2 PQ = unpack2(g_PQ[b][r][a]);
            double uvs = g_UVp[0][b][r][a];
#pragma unroll
            for (int s8 = 1; s8 < 8; s8++) uvs = add2(uvs, g_UVp[s8][b][r][a]);
            float2 UV = unpack2(uvs);
            float Sr = g_S[b][r], Tr = g_T[b][r];
            float fwd = (1.f - ww) * PQ.x - PQ.y + ww * (Sr - pp * rw);
            float bwd = (1.f - ww) * UV.x - UV.y + pp * (Tr - ww * rw);
            float cr = s_wr[r][a];
            s_wr[r][a] = s_pi[r][0] * bwd + s_pi[r][1] * cr + s_pi[r][2] * fwd;
        }
    }
    __syncthreads();

    {
        int w = tid >> 5, lane = tid & 31;
        float acc[2][R] = {{0, 0, 0, 0}, {0, 0, 0, 0}};
#pragma unroll 4
        for (int i = 0; i < 64; i++) {
            int a = i * 16 + w;
            float m0 = g_mem[b][a][lane];
            float m1 = g_mem[b][a][lane + 32];
#pragma unroll
            for (int r = 0; r < R; r++) {
                float wr = s_wr[r][a];
                acc[0][r] = fmaf(wr, m0, acc[0][r]);
                acc[1][r] = fmaf(wr, m1, acc[1][r]);
            }
        }
#pragma unroll
        for (int r = 0; r < R; r++) {
            s_racc[w][r][lane] = acc[0][r];
            s_racc[w][r][lane + 32] = acc[1][r];
        }
    }
    __syncthreads();
    if (tid < R * M) {
        float s = 0.f;
#pragma unroll
        for (int w = 0; w < 16; w++) s += s_racc[w][tid >> 6][tid & 63];
        s_rv[tid] = s;
    }
    __syncthreads();

    {
        int half = tid >> 8, col = tid & 255;
        float acc = 0.f;
        const float* W = W_rd + (size_t)half * 128 * O_OUT + col;
#pragma unroll 8
        for (int j = 0; j < 128; j++)
            acc = fmaf(s_rv[half * 128 + j], W[(size_t)j * O_OUT], acc);
        s_out[half][col] = acc;
    }
    __syncthreads();
    if (tid < O_OUT) {
        out[b * O_OUT + tid] = s_out[0][tid] + s_out[1][tid] + g_outhid[b][tid] + b_rd[tid];
    }
}

// ----------------- launch -----------------
extern "C" void kernel_launch(void* const* d_in, const int* in_sizes, int n_in,
                              void* d_out, int out_size) {
    (void)in_sizes; (void)n_in; (void)out_size;
    const float* x          = (const float*)d_in[0];
    const float* h_prev     = (const float*)d_in[1];
    const float* c_prev     = (const float*)d_in[2];
    const float* mem_prev   = (const float*)d_in[3];
    const float* rw_prev    = (const float*)d_in[4];
    const float* ww_prev    = (const float*)d_in[5];
    const float* usage_prev = (const float*)d_in[6];
    const float* prec_prev  = (const float*)d_in[7];
    const float* link_prev  = (const float*)d_in[8];
    const float* rv_prev    = (const float*)d_in[9];
    const float* Wx         = (const float*)d_in[10];
    const float* Wh         = (const float*)d_in[11];
    const float* b_lstm     = (const float*)d_in[12];
    const float* W_hid      = (const float*)d_in[13];
    const float* b_hid      = (const float*)d_in[14];
    const float* W_if       = (const float*)d_in[15];
    const float* b_if       = (const float*)d_in[16];
    const float* W_rd       = (const float*)d_in[17];
    const float* b_rd       = (const float*)d_in[18];
    float* out = (float*)d_out;

    k1_zpart<<<dim3(4, 32), 256>>>(x, h_prev, rv_prev, Wx, Wh);
    k23_lstm_iface<<<dim3(2, B), 736>>>(c_prev, b_lstm, W_if, W_hid, b_if, b_hid);
    k4b_rank<<<dim3(8, B), 256>>>(rw_prev, ww_prev, usage_prev, mem_prev);
    k57_mem_link<<<dim3(8, B), 512>>>(mem_prev, link_prev, rw_prev, prec_prev);
    k8_read_out<<<B, 512>>>(rw_prev, prec_prev, W_rd, b_rd, out);
}